// round 9
// baseline (speedup 1.0000x reference)
#include <cuda_runtime.h>
#include <cuda_fp16.h>

// Problem constants (fixed shapes per reference)
#define NN 100000
#define EE 1600000
#define FIN 32
#define FHID 64
#define FOUT 32

#define SCAN_B 512
#define NB_MAX 256   // ceil(100000/512)=196 <= 256
#define TILE_W 8     // nodes per warp in k_mlp

// Scratch (device globals — referenced ONLY from device code; host-side use of
// these symbols resolves to the host shadow object on GB300/ATS).
__device__ int    g_deg[NN];
__device__ int    g_rowptr[NN];        // block-local exclusive prefix of deg
__device__ int    g_cur[NN];           // fill cursor, initialized = g_rowptr
__device__ int    g_bsum[NB_MAX];      // per-block sums -> exclusive after last-block scan
__device__ float  g_dinv[NN];
__device__ int    g_col[EE];
__device__ int    g_scan_done = 0;     // last-block ticket (self-resetting)
__device__ __align__(16) __half g_xsh[NN * FIN];        // dinv[v]*x[v]   (fp16)
__device__ __align__(16) __half g_gsh[NN * FOUT];       // dinv[v]*(h@W2) (fp16)
__device__ __align__(16) float  g_ax[(NN + 64) * FIN];  // dinv*(agg xs)  (fp32, padded)

// packed f32x2 helpers
#define FMA2(d, a, b, c) \
    asm("fma.rn.f32x2 %0, %1, %2, %3;" : "=l"(d) : "l"(a), "l"(b), "l"(c))
#define ADD2(d, a, b) \
    asm("add.rn.f32x2 %0, %1, %2;" : "=l"(d) : "l"(a), "l"(b))
#define MUL2(d, a, b) \
    asm("mul.rn.f32x2 %0, %1, %2;" : "=l"(d) : "l"(a), "l"(b))
__device__ __forceinline__ unsigned long long pk2(float a, float b) {
    float2 t = make_float2(a, b);
    return *(unsigned long long*)&t;
}
__device__ __forceinline__ unsigned long long dup2(float a) {
    unsigned long long r;
    asm("mov.b64 %0, {%1, %1};" : "=l"(r) : "r"(__float_as_uint(a)));
    return r;
}
__device__ __forceinline__ float lo2(unsigned long long v) {
    return __uint_as_float((unsigned)(v & 0xffffffffull));
}
__device__ __forceinline__ float hi2(unsigned long long v) {
    return __uint_as_float((unsigned)(v >> 32));
}
__device__ __forceinline__ unsigned long long f2_to_u64(float2 f) {
    return *(unsigned long long*)&f;
}

// ---------------------------------------------------------------------------
// Per-warp inline probe: which of {c0,c1} is edge_index? Edge words are
// unsigned < 100000; fp32 normal bit patterns are >= 2^23 or have sign bit.
__device__ __forceinline__ int probe_is_edges(const void* c0) {
    unsigned idx = (threadIdx.x & 31) * 99991u + (blockIdx.x & 1023) * 131u;
    unsigned v = ((const unsigned*)c0)[idx];  // < 3.2M
    return __all_sync(0xffffffffu, v < 100000u);
}

// ---- degree count: 4 edges per thread (int4) ------------------------------
__global__ void k_count(const void* c0, const void* c1, int e) {
    const int* eptr = probe_is_edges(c0) ? (const int*)c0 : (const int*)c1;
    int i = (blockIdx.x * blockDim.x + threadIdx.x) * 4;
    if (i < e) {
        int4 d4 = *(const int4*)(eptr + e + i);
        if ((unsigned)d4.x < (unsigned)NN) atomicAdd(&g_deg[d4.x], 1);
        if ((unsigned)d4.y < (unsigned)NN) atomicAdd(&g_deg[d4.y], 1);
        if ((unsigned)d4.z < (unsigned)NN) atomicAdd(&g_deg[d4.z], 1);
        if ((unsigned)d4.w < (unsigned)NN) atomicAdd(&g_deg[d4.w], 1);
    }
}

// ---- scan: block-exclusive scan of deg + dinv + fp16 pre-scale; the last
// block to finish also scans the 196 block sums (fused scanB).
__global__ __launch_bounds__(SCAN_B) void k_scan(const void* c0, const void* c1,
                                                 int n, int nb) {
    const float* xptr = probe_is_edges(c0) ? (const float*)c1 : (const float*)c0;
    __shared__ int   s[SCAN_B];
    __shared__ float sdinv[SCAN_B];
    __shared__ int   sB[NB_MAX];
    __shared__ bool  amLast;
    int t = threadIdx.x;
    int i = blockIdx.x * SCAN_B + t;
    int v = (i < n) ? g_deg[i] : 0;
    s[t] = v;
    __syncthreads();
    for (int o = 1; o < SCAN_B; o <<= 1) {
        int x = (t >= o) ? s[t - o] : 0;
        __syncthreads();
        s[t] += x;
        __syncthreads();
    }
    float d = rsqrtf((float)(v + 1));          // +1 self-loop
    if (i < n) {
        int excl = s[t] - v;
        g_rowptr[i] = excl;
        g_cur[i] = excl;                        // fill cursor
        g_dinv[i] = d;
    }
    sdinv[t] = d;
    if (t == SCAN_B - 1) g_bsum[blockIdx.x] = s[t];
    __syncthreads();

    // pre-scale: nodes [b0, b0+512) -> fp16 rows (4096 quads, 8 iters)
    int b0 = blockIdx.x * SCAN_B;
#pragma unroll
    for (int r = 0; r < 8; r++) {
        int ql = t + r * SCAN_B;               // local quad 0..4095
        int nl = ql >> 3;                      // local node
        int node = b0 + nl;
        if (node < n) {
            float4 p = ((const float4*)xptr)[node * 8 + (ql & 7)];
            float dd = sdinv[nl];
            __half2 h0 = __floats2half2_rn(p.x * dd, p.y * dd);
            __half2 h1 = __floats2half2_rn(p.z * dd, p.w * dd);
            uint2 packed;
            packed.x = *(unsigned*)&h0;
            packed.y = *(unsigned*)&h1;
            ((uint2*)g_xsh)[node * 8 + (ql & 7)] = packed;
        }
    }

    // last-block: exclusive scan of the nb block sums
    __threadfence();
    __syncthreads();
    if (t == 0) amLast = (atomicAdd(&g_scan_done, 1) == gridDim.x - 1);
    __syncthreads();
    if (amLast) {
        __threadfence();                        // acquire all bsum writes
        int bv = (t < NB_MAX && t < nb) ? g_bsum[t] : 0;
        if (t < NB_MAX) sB[t] = bv;
        __syncthreads();
        for (int o = 1; o < NB_MAX; o <<= 1) {
            int x = (t >= o && t < NB_MAX) ? sB[t - o] : 0;
            __syncthreads();
            if (t < NB_MAX) sB[t] += x;
            __syncthreads();
        }
        if (t < nb) g_bsum[t] = sB[t] - bv;     // exclusive block offsets
        if (t == 0) g_scan_done = 0;            // reset for next graph replay
    }
}

// global rowptr on the fly
__device__ __forceinline__ int rp(int i, int e) {
    return (i == NN) ? e : (g_rowptr[i] + g_bsum[i >> 9]);
}

// ---- CSR bucket fill: 4 edges per thread ----------------------------------
__global__ void k_fill(const void* c0, const void* c1, int e) {
    const int* eptr = probe_is_edges(c0) ? (const int*)c0 : (const int*)c1;
    int i = (blockIdx.x * blockDim.x + threadIdx.x) * 4;
    if (i < e) {
        int4 s4 = *(const int4*)(eptr + i);
        int4 d4 = *(const int4*)(eptr + e + i);
        if ((unsigned)d4.x < (unsigned)NN)
            g_col[atomicAdd(&g_cur[d4.x], 1) + g_bsum[d4.x >> 9]] = s4.x;
        if ((unsigned)d4.y < (unsigned)NN)
            g_col[atomicAdd(&g_cur[d4.y], 1) + g_bsum[d4.y >> 9]] = s4.y;
        if ((unsigned)d4.z < (unsigned)NN)
            g_col[atomicAdd(&g_cur[d4.z], 1) + g_bsum[d4.z >> 9]] = s4.z;
        if ((unsigned)d4.w < (unsigned)NN)
            g_col[atomicAdd(&g_cur[d4.w], 1) + g_bsum[d4.w >> 9]] = s4.w;
    }
}

// ---- fp16 warp aggregation core v2 ----------------------------------------
// Warp = node v. lane = eslot(2b)<<3 | fq(3b). Per iter: two gathers are
// pair-summed in fp16 (HADD2) before conversion; accumulation uses packed
// f32x2 adds. OOB slots contribute uint2{0,0} = +0.0h (safe). After the
// packed shfl reduce, lanes 0..7 hold quad fq of sum_{u} in[u] + in[v].
__device__ __forceinline__ float4 aggh(const __half* __restrict__ in,
                                       int v, int lane, int beg, int end) {
    int eslot = lane >> 3;
    int fq = lane & 7;
    unsigned long long a01 = 0, a23 = 0;   // packed (f0,f1), (f2,f3)
    for (int k = beg; k < end; k += 8) {
        int i0 = k + eslot;
        int i1 = i0 + 4;
        uint2 r0 = make_uint2(0u, 0u);
        uint2 r1 = make_uint2(0u, 0u);
        if (i0 < end) {
            int u0 = g_col[i0];
            r0 = *(const uint2*)(in + u0 * 32 + fq * 4);
        }
        if (i1 < end) {
            int u1 = g_col[i1];
            r1 = *(const uint2*)(in + u1 * 32 + fq * 4);
        }
        __half2 s0 = __hadd2(*(__half2*)&r0.x, *(__half2*)&r1.x);
        __half2 s1 = __hadd2(*(__half2*)&r0.y, *(__half2*)&r1.y);
        ADD2(a01, a01, f2_to_u64(__half22float2(s0)));
        ADD2(a23, a23, f2_to_u64(__half22float2(s1)));
    }
    if (eslot == 0) {   // self-loop
        uint2 raw = *(const uint2*)(in + v * 32 + fq * 4);
        ADD2(a01, a01, f2_to_u64(__half22float2(*(__half2*)&raw.x)));
        ADD2(a23, a23, f2_to_u64(__half22float2(*(__half2*)&raw.y)));
    }
    // packed tree reduce over eslots (lanes fold down by 16, then 8)
#pragma unroll
    for (int d = 16; d >= 8; d >>= 1) {
        unsigned long long t01 = pk2(
            __uint_as_float(__shfl_down_sync(0xffffffffu, (unsigned)a01, d)),
            __uint_as_float(__shfl_down_sync(0xffffffffu, (unsigned)(a01 >> 32), d)));
        unsigned long long t23 = pk2(
            __uint_as_float(__shfl_down_sync(0xffffffffu, (unsigned)a23, d)),
            __uint_as_float(__shfl_down_sync(0xffffffffu, (unsigned)(a23 >> 32), d)));
        ADD2(a01, a01, t01);
        ADD2(a23, a23, t23);
    }
    return make_float4(lo2(a01), hi2(a01), lo2(a23), hi2(a23));
}

// ---- agg1: warp-per-node gather, low-regs/high-occ: ax = dinv*(agg xs) ----
__global__ __launch_bounds__(256) void k_agg1(int n, int e) {
    int warp = (blockIdx.x * blockDim.x + threadIdx.x) >> 5;
    int lane = threadIdx.x & 31;
    if (warp >= n) return;
    int v = warp;
    float4 acc = aggh(g_xsh, v, lane, rp(v, e), rp(v + 1, e));
    if (lane < 8) {
        unsigned long long dv2 = dup2(g_dinv[v]);
        unsigned long long r01, r23;
        MUL2(r01, dv2, pk2(acc.x, acc.y));
        MUL2(r23, dv2, pk2(acc.z, acc.w));
        float4 r = make_float4(lo2(r01), hi2(r01), lo2(r23), hi2(r23));
        *(float4*)&g_ax[v * 32 + lane * 4] = r;
    }
}

// ---- mlp: dedicated, warp owns TILE_W nodes; weights in regs (phased so
// w1p/w2p lifetimes are disjoint); activations via conflict-free LDS.128
// broadcasts. gs = dinv*(relu(ax@W1+b1)@W2) -> fp16.
__global__ __launch_bounds__(256) void k_mlp(const float* __restrict__ W1,
                                             const float* __restrict__ b1,
                                             const float* __restrict__ W2,
                                             int n) {
    __shared__ __align__(16) float s_ax[8][TILE_W][FIN];
    __shared__ __align__(16) float s_h[8][TILE_W][FHID];

    int wl = threadIdx.x >> 5;
    int lane = threadIdx.x & 31;
    int base = (blockIdx.x * 8 + wl) * TILE_W;
    if (base >= n) return;

    // --- A: stage 8 node rows (g_ax is padded; OOB rows unused) ---
    {
        const float4* src = (const float4*)(g_ax + base * 32);
        float4* dst = (float4*)s_ax[wl];
        dst[lane]      = src[lane];
        dst[lane + 32] = src[lane + 32];
    }
    __syncwarp();

    // --- B: layer 1, weight column-pair (lane, lane+32) in registers ---
    {
        unsigned long long w1p[32];
#pragma unroll
        for (int i = 0; i < 32; i++)
            w1p[i] = pk2(W1[i * 64 + lane], W1[i * 64 + 32 + lane]);
        unsigned long long bpair = pk2(b1[lane], b1[lane + 32]);

#pragma unroll 1
        for (int j = 0; j < TILE_W; j++) {
            if (base + j >= n) break;
            unsigned long long acc = bpair;
            const float4* axv = (const float4*)s_ax[wl][j];
#pragma unroll
            for (int i4 = 0; i4 < 8; i4++) {
                float4 x4 = axv[i4];          // LDS.128 broadcast
                FMA2(acc, dup2(x4.x), w1p[i4 * 4 + 0], acc);
                FMA2(acc, dup2(x4.y), w1p[i4 * 4 + 1], acc);
                FMA2(acc, dup2(x4.z), w1p[i4 * 4 + 2], acc);
                FMA2(acc, dup2(x4.w), w1p[i4 * 4 + 3], acc);
            }
            s_h[wl][j][lane]      = fmaxf(lo2(acc), 0.f);
            s_h[wl][j][lane + 32] = fmaxf(hi2(acc), 0.f);
        }
    }
    __syncwarp();

    // --- C: layer 2, weight row-pair (2i, 2i+1) column lane in registers ---
    {
        unsigned long long w2p[32];
#pragma unroll
        for (int i = 0; i < 32; i++)
            w2p[i] = pk2(W2[(2 * i) * 32 + lane], W2[(2 * i + 1) * 32 + lane]);

#pragma unroll 1
        for (int j = 0; j < TILE_W; j++) {
            int v = base + j;
            if (v >= n) break;
            unsigned long long acc = 0;
            const float4* hv = (const float4*)s_h[wl][j];
#pragma unroll
            for (int i4 = 0; i4 < 16; i4++) {
                float4 h4 = hv[i4];           // LDS.128 broadcast
                FMA2(acc, pk2(h4.x, h4.y), w2p[2 * i4 + 0], acc);
                FMA2(acc, pk2(h4.z, h4.w), w2p[2 * i4 + 1], acc);
            }
            float o = lo2(acc) + hi2(acc);
            g_gsh[v * 32 + lane] = __float2half_rn(g_dinv[v] * o);
        }
    }
}

// ---- layer 2: out = dinv*(agg gs) + b2 -----------------------------------
__global__ __launch_bounds__(256) void k_l2(float* __restrict__ out,
                                            const float* __restrict__ b2,
                                            int n, int e) {
    int warp = (blockIdx.x * blockDim.x + threadIdx.x) >> 5;
    int lane = threadIdx.x & 31;
    if (warp >= n) return;
    int v = warp;

    float4 acc = aggh(g_gsh, v, lane, rp(v, e), rp(v + 1, e));
    if (lane < 8) {
        unsigned long long dv2 = dup2(g_dinv[v]);
        const float4* bqp = (const float4*)b2;   // b2 quad for this fq
        float4 bq = bqp[lane];
        unsigned long long r01, r23;
        FMA2(r01, dv2, pk2(acc.x, acc.y), pk2(bq.x, bq.y));
        FMA2(r23, dv2, pk2(acc.z, acc.w), pk2(bq.z, bq.w));
        float4 r = make_float4(lo2(r01), hi2(r01), lo2(r23), hi2(r23));
        *(float4*)(out + v * 32 + lane * 4) = r;
    }
}

// ---------------------------------------------------------------------------
extern "C" void kernel_launch(void* const* d_in, const int* in_sizes, int n_in,
                              void* d_out, int out_size) {
    // Resolve by element count: 3.2M x2 {x, edge_index} (probed on-device);
    // 2048 x2 W1 then W2; 64 b1; 32 b2.
    const void* big[2] = {nullptr, nullptr}; int nbig = 0;
    const float* W[2] = {nullptr, nullptr};  int nw = 0;
    const float* b1 = nullptr;
    const float* b2 = nullptr;
    for (int i = 0; i < n_in; i++) {
        int s = in_sizes[i];
        if (s == NN * FIN) { if (nbig < 2) big[nbig++] = d_in[i]; }
        else if (s == FIN * FHID) { if (nw < 2) W[nw++] = (const float*)d_in[i]; }
        else if (s == FHID) b1 = (const float*)d_in[i];
        else if (s == FOUT) b2 = (const float*)d_in[i];
    }
    const float* W1 = W[0];
    const float* W2 = W[1];
    float* out = (float*)d_out;

    const int n = NN;
    const int e = EE;
    int nb = (n + SCAN_B - 1) / SCAN_B;   // 196

    // zero g_deg via memset node (true device address, NOT the host shadow)
    void* degAddr = nullptr;
    cudaGetSymbolAddress(&degAddr, g_deg);
    cudaMemsetAsync(degAddr, 0, NN * sizeof(int));

    int eThreads = e / 4;
    k_count<<<(eThreads + 255) / 256, 256>>>(big[0], big[1], e);
    k_scan<<<nb, SCAN_B>>>(big[0], big[1], n, nb);
    k_fill<<<(eThreads + 255) / 256, 256>>>(big[0], big[1], e);

    int aggGrid = (n * 32 + 255) / 256;                 // warp per node
    k_agg1<<<aggGrid, 256>>>(n, e);
    int mlpGrid = (n + 8 * TILE_W - 1) / (8 * TILE_W);  // 64 nodes per CTA
    k_mlp<<<mlpGrid, 256>>>(W1, b1, W2, n);
    k_l2<<<aggGrid, 256>>>(out, b2, n, e);
}